// round 1
// baseline (speedup 1.0000x reference)
#include <cuda_runtime.h>
#include <math.h>

// ---------------- scratch (static device globals; no allocation) ----------------
__device__ float g_col[33554432];   // max: 2*1024*16384 (stage2 cols)
__device__ float g_off[19267584];   // max: 2*147*65536  (stage1 offset conv out)
__device__ float g_tmp[8388608];    // max: 2*64*65536   (stage1 dcn out, pre-norm)
__device__ float g_a[2097152];      // 2*256*64*64 activations
__device__ float g_b[2097152];
__device__ float g_mean[512];
__device__ float g_rstd[512];

// ---------------- im2col (zero or reflect padding) ----------------
// col[n][c*KH*KW + ky*KW + kx][ho*Wo + wo]
__global__ void im2col_kernel(const float* __restrict__ x, float* __restrict__ col,
                              int Cin, int H, int W, int KH, int KW,
                              int stride, int pad, int Ho, int Wo, int reflect)
{
    int npix = Ho * Wo;
    int pix = blockIdx.x * blockDim.x + threadIdx.x;
    if (pix >= npix) return;
    int r = blockIdx.y;            // row in [0, Cin*KH*KW)
    int n = blockIdx.z;
    int kx = r % KW;
    int ky = (r / KW) % KH;
    int c  = r / (KW * KH);
    int ho = pix / Wo, wo = pix % Wo;
    int iy = ho * stride - pad + ky;
    int ix = wo * stride - pad + kx;
    float v;
    if (reflect) {
        if (iy < 0) iy = -iy; else if (iy >= H) iy = 2 * H - 2 - iy;
        if (ix < 0) ix = -ix; else if (ix >= W) ix = 2 * W - 2 - ix;
        v = x[(((size_t)n * Cin + c) * H + iy) * W + ix];
    } else {
        v = (iy >= 0 && iy < H && ix >= 0 && ix < W)
              ? x[(((size_t)n * Cin + c) * H + iy) * W + ix] : 0.0f;
    }
    col[((size_t)n * (Cin * KH * KW) + r) * npix + pix] = v;
}

// ---------------- deformable sampling -> column matrix ----------------
// off layout: [n][3K][npix]: rows [0,K)=oy, [K,2K)=ox, [2K,3K)=mask logits
// col[n][c*K + k][pix] = mask * bilinear(x[n][c], py, px)
__global__ void deform_sample_kernel(const float* __restrict__ x,
                                     const float* __restrict__ off,
                                     float* __restrict__ col,
                                     int Cin, int H, int W, int KH, int KW,
                                     int stride, int pad, int Ho, int Wo)
{
    int npix = Ho * Wo;
    int pix = blockIdx.x * blockDim.x + threadIdx.x;
    if (pix >= npix) return;
    int K = KH * KW;
    int k = blockIdx.y;
    int n = blockIdx.z;
    int ho = pix / Wo, wo = pix % Wo;

    const float* offn = off + (size_t)n * 3 * K * npix;
    float oy = offn[(size_t)k * npix + pix];
    float ox = offn[(size_t)(K + k) * npix + pix];
    float ml = offn[(size_t)(2 * K + k) * npix + pix];
    float m = 1.0f / (1.0f + expf(-ml));

    int ky = k / KW, kx = k % KW;
    float py = (float)(ho * stride - pad + ky) + oy;
    float px = (float)(wo * stride - pad + kx) + ox;
    float y0f = floorf(py), x0f = floorf(px);
    int y0 = (int)y0f, x0 = (int)x0f;
    float wy = py - y0f, wx = px - x0f;

    int y1 = y0 + 1, x1 = x0 + 1;
    float vy0 = (y0 >= 0 && y0 <= H - 1) ? 1.0f : 0.0f;
    float vy1 = (y1 >= 0 && y1 <= H - 1) ? 1.0f : 0.0f;
    float vx0 = (x0 >= 0 && x0 <= W - 1) ? 1.0f : 0.0f;
    float vx1 = (x1 >= 0 && x1 <= W - 1) ? 1.0f : 0.0f;
    int y0c = min(max(y0, 0), H - 1), y1c = min(max(y1, 0), H - 1);
    int x0c = min(max(x0, 0), W - 1), x1c = min(max(x1, 0), W - 1);

    float w00 = (1.0f - wy) * (1.0f - wx) * vy0 * vx0 * m;
    float w01 = (1.0f - wy) * wx          * vy0 * vx1 * m;
    float w10 = wy          * (1.0f - wx) * vy1 * vx0 * m;
    float w11 = wy          * wx          * vy1 * vx1 * m;

    size_t b00 = (size_t)y0c * W + x0c;
    size_t b01 = (size_t)y0c * W + x1c;
    size_t b10 = (size_t)y1c * W + x0c;
    size_t b11 = (size_t)y1c * W + x1c;

    const float* xn = x + (size_t)n * Cin * H * W;
    float* cp = col + (size_t)n * Cin * K * npix + (size_t)k * npix + pix;
    size_t cstride = (size_t)K * npix;
    for (int c = 0; c < Cin; c++) {
        const float* xc = xn + (size_t)c * H * W;
        float v = w00 * xc[b00] + w01 * xc[b01] + w10 * xc[b10] + w11 * xc[b11];
        cp[(size_t)c * cstride] = v;
    }
}

// ---------------- tiled fp32 GEMM + bias:  C[n][M][N] = A[M,K] * B[n][K,N] + bias ----------------
__global__ void gemm_bias_kernel(const float* __restrict__ A,
                                 const float* __restrict__ B,
                                 const float* __restrict__ bias,
                                 float* __restrict__ C,
                                 int M, int Kd, int N)
{
    const int BM = 64, BN = 64, BK = 16;
    __shared__ __align__(16) float As[BK][BM];
    __shared__ __align__(16) float Bs[BK][BN];
    int n = blockIdx.z;
    const float* Bn = B + (size_t)n * Kd * N;
    float* Cn = C + (size_t)n * M * N;
    int bm = blockIdx.y * BM, bn = blockIdx.x * BN;
    int tid = threadIdx.x;
    int tx = tid & 15, ty = tid >> 4;

    float acc[4][4];
#pragma unroll
    for (int i = 0; i < 4; i++)
#pragma unroll
        for (int j = 0; j < 4; j++) acc[i][j] = 0.0f;

    for (int k0 = 0; k0 < Kd; k0 += BK) {
#pragma unroll
        for (int t = 0; t < 4; t++) {
            int idx = tid + t * 256;
            int m_l = idx >> 4;
            int k_l = idx & 15;
            int gm = bm + m_l, gk = k0 + k_l;
            float v = (gm < M && gk < Kd) ? A[(size_t)gm * Kd + gk] : 0.0f;
            As[k_l][m_l] = v;
        }
#pragma unroll
        for (int t = 0; t < 4; t++) {
            int idx = tid + t * 256;
            int k_l = idx >> 6;
            int n_l = idx & 63;
            int gk = k0 + k_l, gn = bn + n_l;
            float v = (gk < Kd) ? Bn[(size_t)gk * N + gn] : 0.0f;
            Bs[k_l][n_l] = v;
        }
        __syncthreads();
#pragma unroll
        for (int kk = 0; kk < BK; kk++) {
            float4 a = *(const float4*)&As[kk][ty * 4];
            float4 b = *(const float4*)&Bs[kk][tx * 4];
            acc[0][0] += a.x * b.x; acc[0][1] += a.x * b.y; acc[0][2] += a.x * b.z; acc[0][3] += a.x * b.w;
            acc[1][0] += a.y * b.x; acc[1][1] += a.y * b.y; acc[1][2] += a.y * b.z; acc[1][3] += a.y * b.w;
            acc[2][0] += a.z * b.x; acc[2][1] += a.z * b.y; acc[2][2] += a.z * b.z; acc[2][3] += a.z * b.w;
            acc[3][0] += a.w * b.x; acc[3][1] += a.w * b.y; acc[3][2] += a.w * b.z; acc[3][3] += a.w * b.w;
        }
        __syncthreads();
    }
#pragma unroll
    for (int i = 0; i < 4; i++) {
        int gm = bm + ty * 4 + i;
        if (gm >= M) continue;
        float bv = bias ? bias[gm] : 0.0f;
#pragma unroll
        for (int j = 0; j < 4; j++) {
            int gn = bn + tx * 4 + j;
            Cn[(size_t)gm * N + gn] = acc[i][j] + bv;
        }
    }
}

// ---------------- instance norm: stats (block per (n,c)) ----------------
__global__ void in_stats_kernel(const float* __restrict__ x,
                                float* __restrict__ mean, float* __restrict__ rstd,
                                int npix)
{
    int nc = blockIdx.x;
    const float* p = x + (size_t)nc * npix;
    double s = 0.0, s2 = 0.0;
    for (int i = threadIdx.x; i < npix; i += blockDim.x) {
        float v = p[i];
        s += v;
        s2 += (double)v * (double)v;
    }
    __shared__ double sh[256], sh2[256];
    sh[threadIdx.x] = s; sh2[threadIdx.x] = s2;
    __syncthreads();
    for (int o = 128; o > 0; o >>= 1) {
        if (threadIdx.x < o) { sh[threadIdx.x] += sh[threadIdx.x + o]; sh2[threadIdx.x] += sh2[threadIdx.x + o]; }
        __syncthreads();
    }
    if (threadIdx.x == 0) {
        double mn = sh[0] / npix;
        double var = sh2[0] / npix - mn * mn;
        mean[nc] = (float)mn;
        rstd[nc] = (float)rsqrt(var + 1e-5);
    }
}

// ---------------- instance norm: apply (optional relu / skip-add) ----------------
__global__ void norm_apply_kernel(const float* __restrict__ x,
                                  const float* __restrict__ mean,
                                  const float* __restrict__ rstd,
                                  const float* __restrict__ skip,
                                  float* __restrict__ out,
                                  int npix, int relu, size_t total)
{
    size_t i = (size_t)blockIdx.x * blockDim.x + threadIdx.x;
    if (i >= total) return;
    int nc = (int)(i / (size_t)npix);
    float v = (x[i] - mean[nc]) * rstd[nc];
    if (skip) v += skip[i];
    if (relu) v = fmaxf(v, 0.0f);
    out[i] = v;
}

// ---------------- launch ----------------
extern "C" void kernel_launch(void* const* d_in, const int* in_sizes, int n_in,
                              void* d_out, int out_size)
{
    (void)in_sizes; (void)n_in; (void)out_size;
    const float* x      = (const float*)d_in[0];
    const float* off1_w = (const float*)d_in[1];
    const float* off1_b = (const float*)d_in[2];
    const float* dcn1_w = (const float*)d_in[3];
    const float* dcn1_b = (const float*)d_in[4];
    const float* off2_w = (const float*)d_in[5];
    const float* off2_b = (const float*)d_in[6];
    const float* dcn2_w = (const float*)d_in[7];
    const float* dcn2_b = (const float*)d_in[8];
    const float* off3_w = (const float*)d_in[9];
    const float* off3_b = (const float*)d_in[10];
    const float* dcn3_w = (const float*)d_in[11];
    const float* dcn3_b = (const float*)d_in[12];
    const float* rb1_w1 = (const float*)d_in[13];
    const float* rb1_b1 = (const float*)d_in[14];
    const float* rb1_w2 = (const float*)d_in[15];
    const float* rb1_b2 = (const float*)d_in[16];
    const float* rb2_w1 = (const float*)d_in[17];
    const float* rb2_b1 = (const float*)d_in[18];
    const float* rb2_w2 = (const float*)d_in[19];
    const float* rb2_b2 = (const float*)d_in[20];

    float* outp  = (float*)d_out;
    float* out_h = outp;                                 // (2,256,64,64)
    float* skip1 = outp + 2097152;                       // (2,64,256,256)
    float* skip2 = outp + 2097152 + 8388608;             // (2,128,128,128)

    float *col, *offb, *tmp, *ga, *gb, *mn, *rs;
    cudaGetSymbolAddress((void**)&col,  g_col);
    cudaGetSymbolAddress((void**)&offb, g_off);
    cudaGetSymbolAddress((void**)&tmp,  g_tmp);
    cudaGetSymbolAddress((void**)&ga,   g_a);
    cudaGetSymbolAddress((void**)&gb,   g_b);
    cudaGetSymbolAddress((void**)&mn,   g_mean);
    cudaGetSymbolAddress((void**)&rs,   g_rstd);

    auto im2col = [&](const float* src, float* dst, int Cin, int H, int W,
                      int KH, int KW, int s, int p, int Ho, int Wo, int refl) {
        int npix = Ho * Wo;
        dim3 grid((npix + 255) / 256, Cin * KH * KW, 2);
        im2col_kernel<<<grid, 256>>>(src, dst, Cin, H, W, KH, KW, s, p, Ho, Wo, refl);
    };
    auto dsample = [&](const float* src, const float* off, float* dst, int Cin, int H, int W,
                       int KH, int KW, int s, int p, int Ho, int Wo) {
        int npix = Ho * Wo;
        dim3 grid((npix + 255) / 256, KH * KW, 2);
        deform_sample_kernel<<<grid, 256>>>(src, off, dst, Cin, H, W, KH, KW, s, p, Ho, Wo);
    };
    auto gemm = [&](const float* W, const float* B, const float* bias, float* C,
                    int M, int K, int N) {
        dim3 grid(N / 64, (M + 63) / 64, 2);
        gemm_bias_kernel<<<grid, 256>>>(W, B, bias, C, M, K, N);
    };
    auto inorm = [&](const float* xin, float* dst, int C, int npix,
                     const float* skip, int relu) {
        in_stats_kernel<<<2 * C, 256>>>(xin, mn, rs, npix);
        size_t total = (size_t)2 * C * npix;
        norm_apply_kernel<<<(unsigned)((total + 255) / 256), 256>>>(xin, mn, rs, skip, dst, npix, relu, total);
    };

    // ===== Stage 1: mdcp(x, 7x7, s1, p3), 3 -> 64, 256x256 =====
    im2col(x, col, 3, 256, 256, 7, 7, 1, 3, 256, 256, 0);
    gemm(off1_w, col, off1_b, offb, 147, 147, 65536);
    dsample(x, offb, col, 3, 256, 256, 7, 7, 1, 3, 256, 256);
    gemm(dcn1_w, col, dcn1_b, tmp, 64, 147, 65536);
    inorm(tmp, skip1, 64, 65536, nullptr, 1);

    // ===== Stage 2: mdcp(h1, 4x4, s2, p1), 64 -> 128, 128x128 =====
    im2col(skip1, col, 64, 256, 256, 4, 4, 2, 1, 128, 128, 0);
    gemm(off2_w, col, off2_b, offb, 48, 1024, 16384);
    dsample(skip1, offb, col, 64, 256, 256, 4, 4, 2, 1, 128, 128);
    gemm(dcn2_w, col, dcn2_b, tmp, 128, 1024, 16384);
    inorm(tmp, skip2, 128, 16384, nullptr, 1);

    // ===== Stage 3: mdcp(h2, 4x4, s2, p1), 128 -> 256, 64x64 =====
    im2col(skip2, col, 128, 128, 128, 4, 4, 2, 1, 64, 64, 0);
    gemm(off3_w, col, off3_b, offb, 48, 2048, 4096);
    dsample(skip2, offb, col, 128, 128, 128, 4, 4, 2, 1, 64, 64);
    gemm(dcn3_w, col, dcn3_b, tmp, 256, 2048, 4096);
    inorm(tmp, ga, 256, 4096, nullptr, 1);

    // ===== Res block 1 (reflect-pad 3x3 convs, 256 ch, 64x64) =====
    im2col(ga, col, 256, 64, 64, 3, 3, 1, 1, 64, 64, 1);
    gemm(rb1_w1, col, rb1_b1, tmp, 256, 2304, 4096);
    inorm(tmp, gb, 256, 4096, nullptr, 1);
    im2col(gb, col, 256, 64, 64, 3, 3, 1, 1, 64, 64, 1);
    gemm(rb1_w2, col, rb1_b2, tmp, 256, 2304, 4096);
    inorm(tmp, ga, 256, 4096, ga, 0);   // ga = ga + IN(conv2)

    // ===== Res block 2 =====
    im2col(ga, col, 256, 64, 64, 3, 3, 1, 1, 64, 64, 1);
    gemm(rb2_w1, col, rb2_b1, tmp, 256, 2304, 4096);
    inorm(tmp, gb, 256, 4096, nullptr, 1);
    im2col(gb, col, 256, 64, 64, 3, 3, 1, 1, 64, 64, 1);
    gemm(rb2_w2, col, rb2_b2, tmp, 256, 2304, 4096);
    inorm(tmp, out_h, 256, 4096, ga, 0);  // h = ga + IN(conv2)
}

// round 3
// speedup vs baseline: 1.6615x; 1.6615x over previous
#include <cuda_runtime.h>
#include <math.h>
#include <stdint.h>

// ---------------- scratch (static device globals; no allocation) ----------------
__device__ float g_col[33554432];   // max: 2*1024*16384 (stage2 cols)
__device__ float g_off[19267584];   // max: 2*147*65536  (stage1 offset conv out)
__device__ float g_tmp[8388608];    // max: 2*64*65536   (stage1 dcn out, pre-norm)
__device__ float g_a[2097152];      // 2*256*64*64 activations
__device__ float g_b[2097152];
__device__ float g_mean[512];
__device__ float g_rstd[512];
__device__ float g_wpad[33760];     // padded stage-1 weights: 147*160 + 64*160

// ---------------- im2col (zero or reflect padding) ----------------
__global__ void im2col_kernel(const float* __restrict__ x, float* __restrict__ col,
                              int Cin, int H, int W, int KH, int KW,
                              int stride, int pad, int Ho, int Wo, int reflect)
{
    int npix = Ho * Wo;
    int pix = blockIdx.x * blockDim.x + threadIdx.x;
    if (pix >= npix) return;
    int r = blockIdx.y;            // row in [0, Cin*KH*KW)
    int n = blockIdx.z;
    int kx = r % KW;
    int ky = (r / KW) % KH;
    int c  = r / (KW * KH);
    int ho = pix / Wo, wo = pix % Wo;
    int iy = ho * stride - pad + ky;
    int ix = wo * stride - pad + kx;
    float v;
    if (reflect) {
        if (iy < 0) iy = -iy; else if (iy >= H) iy = 2 * H - 2 - iy;
        if (ix < 0) ix = -ix; else if (ix >= W) ix = 2 * W - 2 - ix;
        v = x[(((size_t)n * Cin + c) * H + iy) * W + ix];
    } else {
        v = (iy >= 0 && iy < H && ix >= 0 && ix < W)
              ? x[(((size_t)n * Cin + c) * H + iy) * W + ix] : 0.0f;
    }
    col[((size_t)n * (Cin * KH * KW) + r) * npix + pix] = v;
}

// ---------------- deformable sampling -> column matrix ----------------
__global__ void deform_sample_kernel(const float* __restrict__ x,
                                     const float* __restrict__ off,
                                     float* __restrict__ col,
                                     int Cin, int H, int W, int KH, int KW,
                                     int stride, int pad, int Ho, int Wo)
{
    int npix = Ho * Wo;
    int pix = blockIdx.x * blockDim.x + threadIdx.x;
    if (pix >= npix) return;
    int K = KH * KW;
    int k = blockIdx.y;
    int n = blockIdx.z;
    int ho = pix / Wo, wo = pix % Wo;

    const float* offn = off + (size_t)n * 3 * K * npix;
    float oy = offn[(size_t)k * npix + pix];
    float ox = offn[(size_t)(K + k) * npix + pix];
    float ml = offn[(size_t)(2 * K + k) * npix + pix];
    float m = 1.0f / (1.0f + expf(-ml));

    int ky = k / KW, kx = k % KW;
    float py = (float)(ho * stride - pad + ky) + oy;
    float px = (float)(wo * stride - pad + kx) + ox;
    float y0f = floorf(py), x0f = floorf(px);
    int y0 = (int)y0f, x0 = (int)x0f;
    float wy = py - y0f, wx = px - x0f;

    int y1 = y0 + 1, x1 = x0 + 1;
    float vy0 = (y0 >= 0 && y0 <= H - 1) ? 1.0f : 0.0f;
    float vy1 = (y1 >= 0 && y1 <= H - 1) ? 1.0f : 0.0f;
    float vx0 = (x0 >= 0 && x0 <= W - 1) ? 1.0f : 0.0f;
    float vx1 = (x1 >= 0 && x1 <= W - 1) ? 1.0f : 0.0f;
    int y0c = min(max(y0, 0), H - 1), y1c = min(max(y1, 0), H - 1);
    int x0c = min(max(x0, 0), W - 1), x1c = min(max(x1, 0), W - 1);

    float w00 = (1.0f - wy) * (1.0f - wx) * vy0 * vx0 * m;
    float w01 = (1.0f - wy) * wx          * vy0 * vx1 * m;
    float w10 = wy          * (1.0f - wx) * vy1 * vx0 * m;
    float w11 = wy          * wx          * vy1 * vx1 * m;

    size_t b00 = (size_t)y0c * W + x0c;
    size_t b01 = (size_t)y0c * W + x1c;
    size_t b10 = (size_t)y1c * W + x0c;
    size_t b11 = (size_t)y1c * W + x1c;

    const float* xn = x + (size_t)n * Cin * H * W;
    float* cp = col + (size_t)n * Cin * K * npix + (size_t)k * npix + pix;
    size_t cstride = (size_t)K * npix;
    for (int c = 0; c < Cin; c++) {
        const float* xc = xn + (size_t)c * H * W;
        float v = w00 * xc[b00] + w01 * xc[b01] + w10 * xc[b10] + w11 * xc[b11];
        cp[(size_t)c * cstride] = v;
    }
}

// ---------------- weight padding (stage 1: K=147 -> lda=160, zero fill) ----------------
__global__ void pad_weights_kernel(const float* __restrict__ w, float* __restrict__ wp,
                                   int M, int K, int Kp)
{
    int idx = blockIdx.x * blockDim.x + threadIdx.x;
    if (idx >= M * Kp) return;
    int m = idx / Kp, k = idx % Kp;
    wp[idx] = (k < K) ? w[m * K + k] : 0.0f;
}

// ---------------- 3xTF32 tensor-core GEMM + bias (fp32-accurate) ----------------
// C[n][M][N] = A[M,lda(K)] * B[n][K,N] + bias[M]
// BM=128 BN=128 BK=32, 256 threads, 8 warps (2x4), warp tile 64x32, mma m16n8k8.
// Each operand split a = hi + lo (hi = tf32 head, lo exact residual);
// acc += hi*hi + hi*lo + lo*hi  (lo*lo ~2^-22 dropped).
__device__ __forceinline__ uint32_t f2tf32(float f) {
    uint32_t r;
    asm("cvt.rna.tf32.f32 %0, %1;" : "=r"(r) : "f"(f));
    return r;
}
__device__ __forceinline__ void split_tf32(float f, uint32_t& hi, uint32_t& lo) {
    hi = f2tf32(f);
    float res = f - __uint_as_float(hi);
    lo = f2tf32(res);
}

#define AS_STRIDE 36      // 32 + 4 pad : conflict-free fragment LDS
#define BS_STRIDE 136     // 128 + 8 pad
#define AS_BUF (128 * AS_STRIDE)
#define BS_BUF (32 * BS_STRIDE)
#define GEMM_SMEM ((2 * AS_BUF + 2 * BS_BUF) * 4)

extern __shared__ float smem_dyn[];

#define MMA_TF32(acc, a0, a1, a2, a3, b0, b1)                                  \
    asm volatile(                                                              \
        "mma.sync.aligned.m16n8k8.row.col.f32.tf32.tf32.f32 "                  \
        "{%0,%1,%2,%3}, {%4,%5,%6,%7}, {%8,%9}, {%0,%1,%2,%3};\n"              \
        : "+f"(acc[0]), "+f"(acc[1]), "+f"(acc[2]), "+f"(acc[3])               \
        : "r"(a0), "r"(a1), "r"(a2), "r"(a3), "r"(b0), "r"(b1))

__global__ void __launch_bounds__(256, 1)
gemm_tf32_kernel(const float* __restrict__ A, int lda,
                 const float* __restrict__ B,
                 const float* __restrict__ bias,
                 float* __restrict__ C,
                 int M, int Kd, int N)
{
    float* As = smem_dyn;                 // [2][128][36]
    float* Bs = smem_dyn + 2 * AS_BUF;    // [2][32][136]

    int nb = blockIdx.z;
    const float* Bn = B + (size_t)nb * Kd * N;
    float* Cn = C + (size_t)nb * M * N;
    int bm = blockIdx.y * 128, bn = blockIdx.x * 128;
    int tid = threadIdx.x;
    int wid = tid >> 5, lane = tid & 31;
    int warp_m = (wid >> 2) * 64;
    int warp_n = (wid & 3) * 32;
    int lr = lane >> 2, lc = lane & 3;

    float acc[4][4][4];
#pragma unroll
    for (int i = 0; i < 4; i++)
#pragma unroll
        for (int j = 0; j < 4; j++)
#pragma unroll
            for (int q = 0; q < 4; q++) acc[i][j][q] = 0.0f;

    int nk = (Kd + 31) / 32;

    auto load_stage = [&](int kt, int s) {
        int k0 = kt * 32;
#pragma unroll
        for (int t = 0; t < 4; t++) {
            int idx = tid + t * 256;
            int m = idx >> 3;
            int k4 = (idx & 7) << 2;
            int gm = bm + m, gk = k0 + k4;
            const float* src = A + (size_t)gm * lda + gk;
            float* dst = As + s * AS_BUF + m * AS_STRIDE + k4;
            int bytes = 0;
            if (gm < M && gk < Kd) bytes = min(16, (Kd - gk) * 4);
            uint32_t sa = (uint32_t)__cvta_generic_to_shared(dst);
            asm volatile("cp.async.ca.shared.global [%0], [%1], 16, %2;\n"
                         :: "r"(sa), "l"(src), "r"(bytes));
        }
#pragma unroll
        for (int t = 0; t < 4; t++) {
            int idx = tid + t * 256;
            int k = idx >> 5;
            int n4 = (idx & 31) << 2;
            int gk = k0 + k;
            const float* src = Bn + (size_t)gk * N + bn + n4;
            float* dst = Bs + s * BS_BUF + k * BS_STRIDE + n4;
            int bytes = (gk < Kd) ? 16 : 0;
            uint32_t sa = (uint32_t)__cvta_generic_to_shared(dst);
            asm volatile("cp.async.ca.shared.global [%0], [%1], 16, %2;\n"
                         :: "r"(sa), "l"(src), "r"(bytes));
        }
        asm volatile("cp.async.commit_group;\n");
    };

    load_stage(0, 0);

    for (int kt = 0; kt < nk; kt++) {
        int s = kt & 1;
        if (kt + 1 < nk) {
            load_stage(kt + 1, s ^ 1);
            asm volatile("cp.async.wait_group 1;\n");
        } else {
            asm volatile("cp.async.wait_group 0;\n");
        }
        __syncthreads();

        const float* Asb = As + s * AS_BUF;
        const float* Bsb = Bs + s * BS_BUF;
#pragma unroll
        for (int ks = 0; ks < 4; ks++) {
            uint32_t ah[4][4], al[4][4], bh[4][2], bl[4][2];
#pragma unroll
            for (int i = 0; i < 4; i++) {
                const float* ap = Asb + (warp_m + i * 16 + lr) * AS_STRIDE + ks * 8 + lc;
                split_tf32(ap[0],                  ah[i][0], al[i][0]);
                split_tf32(ap[8 * AS_STRIDE],      ah[i][1], al[i][1]);
                split_tf32(ap[4],                  ah[i][2], al[i][2]);
                split_tf32(ap[8 * AS_STRIDE + 4],  ah[i][3], al[i][3]);
            }
#pragma unroll
            for (int j = 0; j < 4; j++) {
                const float* bp = Bsb + (ks * 8 + lc) * BS_STRIDE + warp_n + j * 8 + lr;
                split_tf32(bp[0],              bh[j][0], bl[j][0]);
                split_tf32(bp[4 * BS_STRIDE],  bh[j][1], bl[j][1]);
            }
#pragma unroll
            for (int i = 0; i < 4; i++)
#pragma unroll
                for (int j = 0; j < 4; j++) {
                    MMA_TF32(acc[i][j], ah[i][0], ah[i][1], ah[i][2], ah[i][3],
                             bl[j][0], bl[j][1]);
                    MMA_TF32(acc[i][j], al[i][0], al[i][1], al[i][2], al[i][3],
                             bh[j][0], bh[j][1]);
                    MMA_TF32(acc[i][j], ah[i][0], ah[i][1], ah[i][2], ah[i][3],
                             bh[j][0], bh[j][1]);
                }
        }
        __syncthreads();
    }

    // ---- epilogue: bias + store ----
#pragma unroll
    for (int i = 0; i < 4; i++) {
        int r0 = bm + warp_m + i * 16 + lr;
        int r1 = r0 + 8;
        float bv0 = (r0 < M) ? bias[r0] : 0.0f;
        float bv1 = (r1 < M) ? bias[r1] : 0.0f;
#pragma unroll
        for (int j = 0; j < 4; j++) {
            int cidx = bn + warp_n + j * 8 + lc * 2;
            if (r0 < M) {
                float2 v = make_float2(acc[i][j][0] + bv0, acc[i][j][1] + bv0);
                *(float2*)&Cn[(size_t)r0 * N + cidx] = v;
            }
            if (r1 < M) {
                float2 v = make_float2(acc[i][j][2] + bv1, acc[i][j][3] + bv1);
                *(float2*)&Cn[(size_t)r1 * N + cidx] = v;
            }
        }
    }
}

// ---------------- instance norm: stats ----------------
__global__ void in_stats_kernel(const float* __restrict__ x,
                                float* __restrict__ mean, float* __restrict__ rstd,
                                int npix)
{
    int nc = blockIdx.x;
    const float* p = x + (size_t)nc * npix;
    double s = 0.0, s2 = 0.0;
    for (int i = threadIdx.x; i < npix; i += blockDim.x) {
        float v = p[i];
        s += v;
        s2 += (double)v * (double)v;
    }
    __shared__ double sh[256], sh2[256];
    sh[threadIdx.x] = s; sh2[threadIdx.x] = s2;
    __syncthreads();
    for (int o = 128; o > 0; o >>= 1) {
        if (threadIdx.x < o) { sh[threadIdx.x] += sh[threadIdx.x + o]; sh2[threadIdx.x] += sh2[threadIdx.x + o]; }
        __syncthreads();
    }
    if (threadIdx.x == 0) {
        double mn = sh[0] / npix;
        double var = sh2[0] / npix - mn * mn;
        mean[nc] = (float)mn;
        rstd[nc] = (float)rsqrt(var + 1e-5);
    }
}

// ---------------- instance norm: apply ----------------
__global__ void norm_apply_kernel(const float* __restrict__ x,
                                  const float* __restrict__ mean,
                                  const float* __restrict__ rstd,
                                  const float* __restrict__ skip,
                                  float* __restrict__ out,
                                  int npix, int relu, size_t total)
{
    size_t i = (size_t)blockIdx.x * blockDim.x + threadIdx.x;
    if (i >= total) return;
    int nc = (int)(i / (size_t)npix);
    float v = (x[i] - mean[nc]) * rstd[nc];
    if (skip) v += skip[i];
    if (relu) v = fmaxf(v, 0.0f);
    out[i] = v;
}

// ---------------- launch ----------------
extern "C" void kernel_launch(void* const* d_in, const int* in_sizes, int n_in,
                              void* d_out, int out_size)
{
    (void)in_sizes; (void)n_in; (void)out_size;
    const float* x      = (const float*)d_in[0];
    const float* off1_w = (const float*)d_in[1];
    const float* off1_b = (const float*)d_in[2];
    const float* dcn1_w = (const float*)d_in[3];
    const float* dcn1_b = (const float*)d_in[4];
    const float* off2_w = (const float*)d_in[5];
    const float* off2_b = (const float*)d_in[6];
    const float* dcn2_w = (const float*)d_in[7];
    const float* dcn2_b = (const float*)d_in[8];
    const float* off3_w = (const float*)d_in[9];
    const float* off3_b = (const float*)d_in[10];
    const float* dcn3_w = (const float*)d_in[11];
    const float* dcn3_b = (const float*)d_in[12];
    const float* rb1_w1 = (const float*)d_in[13];
    const float* rb1_b1 = (const float*)d_in[14];
    const float* rb1_w2 = (const float*)d_in[15];
    const float* rb1_b2 = (const float*)d_in[16];
    const float* rb2_w1 = (const float*)d_in[17];
    const float* rb2_b1 = (const float*)d_in[18];
    const float* rb2_w2 = (const float*)d_in[19];
    const float* rb2_b2 = (const float*)d_in[20];

    float* outp  = (float*)d_out;
    float* out_h = outp;                                 // (2,256,64,64)
    float* skip1 = outp + 2097152;                       // (2,64,256,256)
    float* skip2 = outp + 2097152 + 8388608;             // (2,128,128,128)

    float *col, *offb, *tmp, *ga, *gb, *mn, *rs, *wpad;
    cudaGetSymbolAddress((void**)&col,  g_col);
    cudaGetSymbolAddress((void**)&offb, g_off);
    cudaGetSymbolAddress((void**)&tmp,  g_tmp);
    cudaGetSymbolAddress((void**)&ga,   g_a);
    cudaGetSymbolAddress((void**)&gb,   g_b);
    cudaGetSymbolAddress((void**)&mn,   g_mean);
    cudaGetSymbolAddress((void**)&rs,   g_rstd);
    cudaGetSymbolAddress((void**)&wpad, g_wpad);
    float* off1p = wpad;             // 147 x 160
    float* dcn1p = wpad + 147 * 160; // 64 x 160

    static bool attr_set = false;
    if (!attr_set) {
        cudaFuncSetAttribute(gemm_tf32_kernel,
                             cudaFuncAttributeMaxDynamicSharedMemorySize, GEMM_SMEM);
        attr_set = true;
    }

    auto im2col = [&](const float* src, float* dst, int Cin, int H, int W,
                      int KH, int KW, int s, int p, int Ho, int Wo, int refl) {
        int npix = Ho * Wo;
        dim3 grid((npix + 255) / 256, Cin * KH * KW, 2);
        im2col_kernel<<<grid, 256>>>(src, dst, Cin, H, W, KH, KW, s, p, Ho, Wo, refl);
    };
    auto dsample = [&](const float* src, const float* off, float* dst, int Cin, int H, int W,
                       int KH, int KW, int s, int p, int Ho, int Wo) {
        int npix = Ho * Wo;
        dim3 grid((npix + 255) / 256, KH * KW, 2);
        deform_sample_kernel<<<grid, 256>>>(src, off, dst, Cin, H, W, KH, KW, s, p, Ho, Wo);
    };
    auto gemm = [&](const float* W, int lda, const float* B, const float* bias, float* C,
                    int M, int K, int N) {
        dim3 grid(N / 128, (M + 127) / 128, 2);
        gemm_tf32_kernel<<<grid, 256, GEMM_SMEM>>>(W, lda, B, bias, C, M, K, N);
    };
    auto inorm = [&](const float* xin, float* dst, int C, int npix,
                     const float* skip, int relu) {
        in_stats_kernel<<<2 * C, 256>>>(xin, mn, rs, npix);
        size_t total = (size_t)2 * C * npix;
        norm_apply_kernel<<<(unsigned)((total + 255) / 256), 256>>>(xin, mn, rs, skip, dst, npix, relu, total);
    };

    // pack stage-1 weights (K=147 -> lda=160, zero-filled)
    pad_weights_kernel<<<(147 * 160 + 255) / 256, 256>>>(off1_w, off1p, 147, 147, 160);
    pad_weights_kernel<<<(64 * 160 + 255) / 256, 256>>>(dcn1_w, dcn1p, 64, 147, 160);

    // ===== Stage 1: mdcp(x, 7x7, s1, p3), 3 -> 64, 256x256 =====
    im2col(x, col, 3, 256, 256, 7, 7, 1, 3, 256, 256, 0);
    gemm(off1p, 160, col, off1_b, offb, 147, 147, 65536);
    dsample(x, offb, col, 3, 256, 256, 7, 7, 1, 3, 256, 256);
    gemm(dcn1p, 160, col, dcn1_b, tmp, 64, 147, 65536);
    inorm(tmp, skip1, 64, 65536, nullptr, 1);

    // ===== Stage 2: mdcp(h1, 4x4, s2, p1), 64 -> 128, 128x128 =====
    im2col(skip1, col, 64, 256, 256, 4, 4, 2, 1, 128, 128, 0);
    gemm(off2_w, 1024, col, off2_b, offb, 48, 1024, 16384);
    dsample(skip1, offb, col, 64, 256, 256, 4, 4, 2, 1, 128, 128);
    gemm(dcn2_w, 1024, col, dcn2_b, tmp, 128, 1024, 16384);
    inorm(tmp, skip2, 128, 16384, nullptr, 1);

    // ===== Stage 3: mdcp(h2, 4x4, s2, p1), 128 -> 256, 64x64 =====
    im2col(skip2, col, 128, 128, 128, 4, 4, 2, 1, 64, 64, 0);
    gemm(off3_w, 2048, col, off3_b, offb, 48, 2048, 4096);
    dsample(skip2, offb, col, 128, 128, 128, 4, 4, 2, 1, 64, 64);
    gemm(dcn3_w, 2048, col, dcn3_b, tmp, 256, 2048, 4096);
    inorm(tmp, ga, 256, 4096, nullptr, 1);

    // ===== Res block 1 (reflect-pad 3x3 convs, 256 ch, 64x64) =====
    im2col(ga, col, 256, 64, 64, 3, 3, 1, 1, 64, 64, 1);
    gemm(rb1_w1, 2304, col, rb1_b1, tmp, 256, 2304, 4096);
    inorm(tmp, gb, 256, 4096, nullptr, 1);
    im2col(gb, col, 256, 64, 64, 3, 3, 1, 1, 64, 64, 1);
    gemm(rb1_w2, 2304, col, rb1_b2, tmp, 256, 2304, 4096);
    inorm(tmp, ga, 256, 4096, ga, 0);   // ga = ga + IN(conv2)

    // ===== Res block 2 =====
    im2col(ga, col, 256, 64, 64, 3, 3, 1, 1, 64, 64, 1);
    gemm(rb2_w1, 2304, col, rb2_b1, tmp, 256, 2304, 4096);
    inorm(tmp, gb, 256, 4096, nullptr, 1);
    im2col(gb, col, 256, 64, 64, 3, 3, 1, 1, 64, 64, 1);
    gemm(rb2_w2, 2304, col, rb2_b2, tmp, 256, 2304, 4096);
    inorm(tmp, out_h, 256, 4096, ga, 0);  // h = ga + IN(conv2)
}

// round 4
// speedup vs baseline: 2.2544x; 1.3568x over previous
#include <cuda_runtime.h>
#include <math.h>
#include <stdint.h>

// ---------------- scratch (static device globals; no allocation) ----------------
__device__ float g_col[33554432];   // dsample cols (max stage2: 2*1024*16384)
__device__ float g_off[19267584];   // offset conv out (max stage1: 2*147*65536)
__device__ float g_tmp[8388608];    // dcn out pre-norm (max stage1: 2*64*65536)
__device__ float g_a[2097152];
__device__ float g_b[2097152];
__device__ float g_mean[512];
__device__ float g_rstd[512];
__device__ float g_wpad[33760];     // stage-1 weights padded to lda=160

// ---------------- deformable sampling -> column matrix ----------------
__global__ void deform_sample_kernel(const float* __restrict__ x,
                                     const float* __restrict__ off,
                                     float* __restrict__ col,
                                     int Cin, int H, int W, int KH, int KW,
                                     int stride, int pad, int Ho, int Wo)
{
    int npix = Ho * Wo;
    int pix = blockIdx.x * blockDim.x + threadIdx.x;
    if (pix >= npix) return;
    int K = KH * KW;
    int k = blockIdx.y;
    int n = blockIdx.z;
    int ho = pix / Wo, wo = pix % Wo;

    const float* offn = off + (size_t)n * 3 * K * npix;
    float oy = offn[(size_t)k * npix + pix];
    float ox = offn[(size_t)(K + k) * npix + pix];
    float ml = offn[(size_t)(2 * K + k) * npix + pix];
    float m = 1.0f / (1.0f + expf(-ml));

    int ky = k / KW, kx = k % KW;
    float py = (float)(ho * stride - pad + ky) + oy;
    float px = (float)(wo * stride - pad + kx) + ox;
    float y0f = floorf(py), x0f = floorf(px);
    int y0 = (int)y0f, x0 = (int)x0f;
    float wy = py - y0f, wx = px - x0f;

    int y1 = y0 + 1, x1 = x0 + 1;
    float vy0 = (y0 >= 0 && y0 <= H - 1) ? 1.0f : 0.0f;
    float vy1 = (y1 >= 0 && y1 <= H - 1) ? 1.0f : 0.0f;
    float vx0 = (x0 >= 0 && x0 <= W - 1) ? 1.0f : 0.0f;
    float vx1 = (x1 >= 0 && x1 <= W - 1) ? 1.0f : 0.0f;
    int y0c = min(max(y0, 0), H - 1), y1c = min(max(y1, 0), H - 1);
    int x0c = min(max(x0, 0), W - 1), x1c = min(max(x1, 0), W - 1);

    float w00 = (1.0f - wy) * (1.0f - wx) * vy0 * vx0 * m;
    float w01 = (1.0f - wy) * wx          * vy0 * vx1 * m;
    float w10 = wy          * (1.0f - wx) * vy1 * vx0 * m;
    float w11 = wy          * wx          * vy1 * vx1 * m;

    size_t b00 = (size_t)y0c * W + x0c;
    size_t b01 = (size_t)y0c * W + x1c;
    size_t b10 = (size_t)y1c * W + x0c;
    size_t b11 = (size_t)y1c * W + x1c;

    const float* xn = x + (size_t)n * Cin * H * W;
    float* cp = col + (size_t)n * Cin * K * npix + (size_t)k * npix + pix;
    size_t cstride = (size_t)K * npix;
    for (int c = 0; c < Cin; c++) {
        const float* xc = xn + (size_t)c * H * W;
        float v = w00 * xc[b00] + w01 * xc[b01] + w10 * xc[b10] + w11 * xc[b11];
        cp[(size_t)c * cstride] = v;
    }
}

// ---------------- weight padding (stage 1: K=147 -> lda=160) ----------------
__global__ void pad_weights_kernel(const float* __restrict__ w, float* __restrict__ wp,
                                   int M, int K, int Kp)
{
    int idx = blockIdx.x * blockDim.x + threadIdx.x;
    if (idx >= M * Kp) return;
    int m = idx / Kp, k = idx % Kp;
    wp[idx] = (k < K) ? w[m * K + k] : 0.0f;
}

// ---------------- 3xTF32 implicit-conv / GEMM kernel ----------------
// MODE 0: B = precomputed col matrix [n][K][N]
// MODE 1: implicit conv, zero padding  (B = input tensor NCHW)
// MODE 2: implicit conv, reflect padding
struct ConvGeom { int Cin, H, W, KH, KW, KKW, stride, pad, Wo; };

__device__ __forceinline__ uint32_t f2tf32(float f) {
    uint32_t r;
    asm("cvt.rna.tf32.f32 %0, %1;" : "=r"(r) : "f"(f));
    return r;
}
__device__ __forceinline__ void split_tf32(float f, uint32_t& hi, uint32_t& lo) {
    hi = f2tf32(f);
    float res = f - __uint_as_float(hi);
    lo = f2tf32(res);
}

#define AS_STRIDE 36
#define BS_STRIDE 136
#define BS_BUF (32 * BS_STRIDE)

extern __shared__ float smem_dyn[];

#define MMA_TF32(acc, a0, a1, a2, a3, b0, b1)                                  \
    asm volatile(                                                              \
        "mma.sync.aligned.m16n8k8.row.col.f32.tf32.tf32.f32 "                  \
        "{%0,%1,%2,%3}, {%4,%5,%6,%7}, {%8,%9}, {%0,%1,%2,%3};\n"              \
        : "+f"(acc[0]), "+f"(acc[1]), "+f"(acc[2]), "+f"(acc[3])               \
        : "r"(a0), "r"(a1), "r"(a2), "r"(a3), "r"(b0), "r"(b1))

template <int BM, int MODE>
__global__ void __launch_bounds__(256, 1)
gemm_conv_kernel(const float* __restrict__ A, int lda,
                 const float* __restrict__ B,
                 const float* __restrict__ bias,
                 float* __restrict__ C,
                 int M, int Kd, int N, ConvGeom g)
{
    constexpr int AS_BUF = BM * AS_STRIDE;
    constexpr int IMAX = BM / 32;         // 16-row fragment blocks per warp
    float* As = smem_dyn;                 // [2][BM][36]
    float* Bs = smem_dyn + 2 * AS_BUF;    // [2][32][136]

    int nb = blockIdx.z;
    float* Cn = C + (size_t)nb * M * N;
    int bm = blockIdx.y * BM, bn = blockIdx.x * 128;
    int tid = threadIdx.x;
    int wid = tid >> 5, lane = tid & 31;
    int warp_m = (wid >> 2) * (BM / 2);
    int warp_n = (wid & 3) * 32;
    int lr = lane >> 2, lc = lane & 3;

    float acc[IMAX][4][4];
#pragma unroll
    for (int i = 0; i < IMAX; i++)
#pragma unroll
        for (int j = 0; j < 4; j++)
#pragma unroll
            for (int q = 0; q < 4; q++) acc[i][j][q] = 0.0f;

    int nk = (Kd + 31) / 32;

    // ---- A loader (always cp.async, 16B) ----
    auto loadA = [&](int kt, int s) {
        int k0 = kt * 32;
        constexpr int ACP = BM / 32;
#pragma unroll
        for (int t = 0; t < ACP; t++) {
            int idx = tid + t * 256;
            int m = idx >> 3;
            int k4 = (idx & 7) << 2;
            int gm = bm + m, gk = k0 + k4;
            const float* src = A + (size_t)gm * lda + gk;
            float* dst = As + s * AS_BUF + m * AS_STRIDE + k4;
            int bytes = (gm < M && gk < Kd) ? min(16, (Kd - gk) * 4) : 0;
            uint32_t sa = (uint32_t)__cvta_generic_to_shared(dst);
            asm volatile("cp.async.ca.shared.global [%0], [%1], 16, %2;\n"
                         :: "r"(sa), "l"(src), "r"(bytes));
        }
    };

    // ---- B loader MODE 0 (cp.async from col matrix) ----
    auto loadB_col = [&](int kt, int s) {
        const float* Bn = B + (size_t)nb * Kd * N;
        int k0 = kt * 32;
#pragma unroll
        for (int t = 0; t < 4; t++) {
            int idx = tid + t * 256;
            int k = idx >> 5;
            int n4 = (idx & 31) << 2;
            int gk = k0 + k;
            const float* src = Bn + (size_t)gk * N + bn + n4;
            float* dst = Bs + s * BS_BUF + k * BS_STRIDE + n4;
            int bytes = (gk < Kd) ? 16 : 0;
            uint32_t sa = (uint32_t)__cvta_generic_to_shared(dst);
            asm volatile("cp.async.ca.shared.global [%0], [%1], 16, %2;\n"
                         :: "r"(sa), "l"(src), "r"(bytes));
        }
    };

    // ---- B gather MODE 1/2: thread -> one k-row, 16 contiguous columns ----
    // (Wo and col-base are multiples of 16, so the 16 cols share one image row)
    auto gatherB = [&](int kt, float* pref) {
        int k_l = tid >> 3;
        int cb = (tid & 7) << 4;
        int gk = kt * 32 + k_l;
        bool kv = gk < Kd;
        int kk = kv ? gk : 0;
        int c = kk / g.KKW;
        int r = kk - c * g.KKW;
        int ky = r / g.KW;
        int kx = r - ky * g.KW;
        int pix = bn + cb;
        int ho = pix / g.Wo;
        int wo = pix - ho * g.Wo;
        int iy = ho * g.stride - g.pad + ky;
        int ix0 = wo * g.stride - g.pad + kx;
        const float* xc = B + ((size_t)nb * g.Cin + c) * g.H * g.W;
        if (MODE == 2) {
            if (iy < 0) iy = -iy; else if (iy >= g.H) iy = 2 * g.H - 2 - iy;
            const float* rowp = xc + (size_t)iy * g.W;
#pragma unroll
            for (int i = 0; i < 16; i++) {
                int ix = ix0 + i * g.stride;
                if (ix < 0) ix = -ix; else if (ix >= g.W) ix = 2 * g.W - 2 - ix;
                pref[i] = kv ? __ldg(rowp + ix) : 0.0f;
            }
        } else {
            bool rok = kv && iy >= 0 && iy < g.H;
            const float* rowp = xc + (size_t)max(iy, 0) * g.W;
#pragma unroll
            for (int i = 0; i < 16; i++) {
                int ix = ix0 + i * g.stride;
                pref[i] = (rok && ix >= 0 && ix < g.W) ? __ldg(rowp + ix) : 0.0f;
            }
        }
    };
    auto stsB = [&](const float* pref, int s) {
        int k_l = tid >> 3;
        int cb = (tid & 7) << 4;
        float* dst = Bs + s * BS_BUF + k_l * BS_STRIDE + cb;
#pragma unroll
        for (int i = 0; i < 16; i++) dst[i] = pref[i];
    };

    // ---- prologue: stage 0 ----
    loadA(0, 0);
    if (MODE == 0) {
        loadB_col(0, 0);
    } else {
        float pref[16];
        gatherB(0, pref);
        stsB(pref, 0);
    }
    asm volatile("cp.async.commit_group;\n");

    for (int kt = 0; kt < nk; kt++) {
        int s = kt & 1;
        float pref[16];
        bool do_pref = (kt + 1 < nk);
        if (do_pref) {
            loadA(kt + 1, s ^ 1);
            if (MODE == 0) loadB_col(kt + 1, s ^ 1);
            asm volatile("cp.async.commit_group;\n");
            if (MODE != 0) gatherB(kt + 1, pref);   // LDG latency hidden by MMA below
            asm volatile("cp.async.wait_group 1;\n");
        } else {
            asm volatile("cp.async.wait_group 0;\n");
        }
        __syncthreads();

        const float* Asb = As + s * AS_BUF;
        const float* Bsb = Bs + s * BS_BUF;
#pragma unroll
        for (int ks = 0; ks < 4; ks++) {
            uint32_t ah[IMAX][4], al[IMAX][4], bh[4][2], bl[4][2];
#pragma unroll
            for (int i = 0; i < IMAX; i++) {
                const float* ap = Asb + (warp_m + i * 16 + lr) * AS_STRIDE + ks * 8 + lc;
                split_tf32(ap[0],                 ah[i][0], al[i][0]);
                split_tf32(ap[8 * AS_STRIDE],     ah[i][1], al[i][1]);
                split_tf32(ap[4],                 ah[i][2], al[i][2]);
                split_tf32(ap[8 * AS_STRIDE + 4], ah[i][3], al[i][3]);
            }
#pragma unroll
            for (int j = 0; j < 4; j++) {
                const float* bp = Bsb + (ks * 8 + lc) * BS_STRIDE + warp_n + j * 8 + lr;
                split_tf32(bp[0],             bh[j][0], bl[j][0]);
                split_tf32(bp[4 * BS_STRIDE], bh[j][1], bl[j][1]);
            }
#pragma unroll
            for (int i = 0; i < IMAX; i++)
#pragma unroll
                for (int j = 0; j < 4; j++) {
                    MMA_TF32(acc[i][j], ah[i][0], ah[i][1], ah[i][2], ah[i][3],
                             bl[j][0], bl[j][1]);
                    MMA_TF32(acc[i][j], al[i][0], al[i][1], al[i][2], al[i][3],
                             bh[j][0], bh[j][1]);
                    MMA_TF32(acc[i][j], ah[i][0], ah[i][1], ah[i][2], ah[i][3],
                             bh[j][0], bh[j][1]);
                }
        }
        if (MODE != 0 && do_pref) stsB(pref, s ^ 1);
        __syncthreads();
    }

    // ---- epilogue: bias + store ----
#pragma unroll
    for (int i = 0; i < IMAX; i++) {
        int r0 = bm + warp_m + i * 16 + lr;
        int r1 = r0 + 8;
        float bv0 = (r0 < M) ? bias[r0] : 0.0f;
        float bv1 = (r1 < M) ? bias[r1] : 0.0f;
#pragma unroll
        for (int j = 0; j < 4; j++) {
            int cidx = bn + warp_n + j * 8 + lc * 2;
            if (r0 < M) {
                float2 v = make_float2(acc[i][j][0] + bv0, acc[i][j][1] + bv0);
                *(float2*)&Cn[(size_t)r0 * N + cidx] = v;
            }
            if (r1 < M) {
                float2 v = make_float2(acc[i][j][2] + bv1, acc[i][j][3] + bv1);
                *(float2*)&Cn[(size_t)r1 * N + cidx] = v;
            }
        }
    }
}

// ---------------- instance norm: stats ----------------
__global__ void in_stats_kernel(const float* __restrict__ x,
                                float* __restrict__ mean, float* __restrict__ rstd,
                                int npix)
{
    int nc = blockIdx.x;
    const float* p = x + (size_t)nc * npix;
    double s = 0.0, s2 = 0.0;
    for (int i = threadIdx.x; i < npix; i += blockDim.x) {
        float v = p[i];
        s += v;
        s2 += (double)v * (double)v;
    }
    __shared__ double sh[256], sh2[256];
    sh[threadIdx.x] = s; sh2[threadIdx.x] = s2;
    __syncthreads();
    for (int o = 128; o > 0; o >>= 1) {
        if (threadIdx.x < o) { sh[threadIdx.x] += sh[threadIdx.x + o]; sh2[threadIdx.x] += sh2[threadIdx.x + o]; }
        __syncthreads();
    }
    if (threadIdx.x == 0) {
        double mn = sh[0] / npix;
        double var = sh2[0] / npix - mn * mn;
        mean[nc] = (float)mn;
        rstd[nc] = (float)rsqrt(var + 1e-5);
    }
}

// ---------------- instance norm: apply ----------------
__global__ void norm_apply_kernel(const float* __restrict__ x,
                                  const float* __restrict__ mean,
                                  const float* __restrict__ rstd,
                                  const float* __restrict__ skip,
                                  float* __restrict__ out,
                                  int npix, int relu, size_t total)
{
    size_t i = (size_t)blockIdx.x * blockDim.x + threadIdx.x;
    if (i >= total) return;
    int nc = (int)(i / (size_t)npix);
    float v = (x[i] - mean[nc]) * rstd[nc];
    if (skip) v += skip[i];
    if (relu) v = fmaxf(v, 0.0f);
    out[i] = v;
}

// ---------------- launch ----------------
static inline int smem_for(int BM) { return (2 * BM * AS_STRIDE + 2 * BS_BUF) * 4; }

extern "C" void kernel_launch(void* const* d_in, const int* in_sizes, int n_in,
                              void* d_out, int out_size)
{
    (void)in_sizes; (void)n_in; (void)out_size;
    const float* x      = (const float*)d_in[0];
    const float* off1_b = (const float*)d_in[2];
    const float* dcn1_b = (const float*)d_in[4];
    const float* off2_w = (const float*)d_in[5];
    const float* off2_b = (const float*)d_in[6];
    const float* dcn2_w = (const float*)d_in[7];
    const float* dcn2_b = (const float*)d_in[8];
    const float* off3_w = (const float*)d_in[9];
    const float* off3_b = (const float*)d_in[10];
    const float* dcn3_w = (const float*)d_in[11];
    const float* dcn3_b = (const float*)d_in[12];
    const float* rb1_w1 = (const float*)d_in[13];
    const float* rb1_b1 = (const float*)d_in[14];
    const float* rb1_w2 = (const float*)d_in[15];
    const float* rb1_b2 = (const float*)d_in[16];
    const float* rb2_w1 = (const float*)d_in[17];
    const float* rb2_b1 = (const float*)d_in[18];
    const float* rb2_w2 = (const float*)d_in[19];
    const float* rb2_b2 = (const float*)d_in[20];
    const float* off1_w = (const float*)d_in[1];
    const float* dcn1_w = (const float*)d_in[3];

    float* outp  = (float*)d_out;
    float* out_h = outp;
    float* skip1 = outp + 2097152;
    float* skip2 = outp + 2097152 + 8388608;

    float *col, *offb, *tmp, *ga, *gb, *mn, *rs, *wpad;
    cudaGetSymbolAddress((void**)&col,  g_col);
    cudaGetSymbolAddress((void**)&offb, g_off);
    cudaGetSymbolAddress((void**)&tmp,  g_tmp);
    cudaGetSymbolAddress((void**)&ga,   g_a);
    cudaGetSymbolAddress((void**)&gb,   g_b);
    cudaGetSymbolAddress((void**)&mn,   g_mean);
    cudaGetSymbolAddress((void**)&rs,   g_rstd);
    cudaGetSymbolAddress((void**)&wpad, g_wpad);
    float* off1p = wpad;             // 147 x 160
    float* dcn1p = wpad + 147 * 160; // 64 x 160

    static bool attr_set = false;
    if (!attr_set) {
        cudaFuncSetAttribute(gemm_conv_kernel<64, 0>,  cudaFuncAttributeMaxDynamicSharedMemorySize, smem_for(64));
        cudaFuncSetAttribute(gemm_conv_kernel<128, 0>, cudaFuncAttributeMaxDynamicSharedMemorySize, smem_for(128));
        cudaFuncSetAttribute(gemm_conv_kernel<64, 1>,  cudaFuncAttributeMaxDynamicSharedMemorySize, smem_for(64));
        cudaFuncSetAttribute(gemm_conv_kernel<128, 2>, cudaFuncAttributeMaxDynamicSharedMemorySize, smem_for(128));
        attr_set = true;
    }

    ConvGeom g0 = {};   // unused for MODE 0

    auto dsample = [&](const float* src, const float* off, float* dst, int Cin, int H, int W,
                       int KH, int KW, int s, int p, int Ho, int Wo) {
        int npix = Ho * Wo;
        dim3 grid((npix + 255) / 256, KH * KW, 2);
        deform_sample_kernel<<<grid, 256>>>(src, off, dst, Cin, H, W, KH, KW, s, p, Ho, Wo);
    };
    // MODE 0 GEMM on col matrix
    auto gemm_col = [&](const float* W, int lda, const float* B, const float* bias, float* C,
                        int M, int K, int N) {
        if (M <= 64) {
            dim3 grid(N / 128, 1, 2);
            gemm_conv_kernel<64, 0><<<grid, 256, smem_for(64)>>>(W, lda, B, bias, C, M, K, N, g0);
        } else {
            dim3 grid(N / 128, (M + 127) / 128, 2);
            gemm_conv_kernel<128, 0><<<grid, 256, smem_for(128)>>>(W, lda, B, bias, C, M, K, N, g0);
        }
    };
    // implicit conv, zero pad (BM=64)
    auto conv_zero = [&](const float* W, int lda, const float* X, const float* bias, float* C,
                         int M, int K, int N, ConvGeom g) {
        dim3 grid(N / 128, (M + 63) / 64, 2);
        gemm_conv_kernel<64, 1><<<grid, 256, smem_for(64)>>>(W, lda, X, bias, C, M, K, N, g);
    };
    // implicit conv, reflect pad (BM=128)
    auto conv_refl = [&](const float* W, int lda, const float* X, const float* bias, float* C,
                         int M, int K, int N, ConvGeom g) {
        dim3 grid(N / 128, (M + 127) / 128, 2);
        gemm_conv_kernel<128, 2><<<grid, 256, smem_for(128)>>>(W, lda, X, bias, C, M, K, N, g);
    };
    auto inorm = [&](const float* xin, float* dst, int C, int npix,
                     const float* skip, int relu) {
        in_stats_kernel<<<2 * C, 256>>>(xin, mn, rs, npix);
        size_t total = (size_t)2 * C * npix;
        norm_apply_kernel<<<(unsigned)((total + 255) / 256), 256>>>(xin, mn, rs, skip, dst, npix, relu, total);
    };

    // pack stage-1 weights (K=147 -> lda=160 for 16B-aligned cp.async)
    pad_weights_kernel<<<(147 * 160 + 255) / 256, 256>>>(off1_w, off1p, 147, 147, 160);
    pad_weights_kernel<<<(64 * 160 + 255) / 256, 256>>>(dcn1_w, dcn1p, 64, 147, 160);

    // ===== Stage 1: mdcp(x, 7x7, s1, p3), 3 -> 64, 256x256 =====
    ConvGeom g1 = {3, 256, 256, 7, 7, 49, 1, 3, 256};
    conv_zero(off1p, 160, x, off1_b, offb, 147, 147, 65536, g1);
    dsample(x, offb, col, 3, 256, 256, 7, 7, 1, 3, 256, 256);
    gemm_col(dcn1p, 160, col, dcn1_b, tmp, 64, 147, 65536);
    inorm(tmp, skip1, 64, 65536, nullptr, 1);

    // ===== Stage 2: mdcp(h1, 4x4, s2, p1), 64 -> 128, 128x128 =====
    ConvGeom g2 = {64, 256, 256, 4, 4, 16, 2, 1, 128};
    conv_zero(off2_w, 1024, skip1, off2_b, offb, 48, 1024, 16384, g2);
    dsample(skip1, offb, col, 64, 256, 256, 4, 4, 2, 1, 128, 128);
    gemm_col(dcn2_w, 1024, col, dcn2_b, tmp, 128, 1024, 16384);
    inorm(tmp, skip2, 128, 16384, nullptr, 1);

    // ===== Stage 3: mdcp(h2, 4x4, s2, p1), 128 -> 256, 64x64 =====
    ConvGeom g3 = {128, 128, 128, 4, 4, 16, 2, 1, 64};
    conv_zero(off3_w, 2048, skip2, off3_b, offb, 48, 2048, 4096, g3);
    dsample(skip2, offb, col, 128, 128, 128, 4, 4, 2, 1, 64, 64);
    gemm_col(dcn3_w, 2048, col, dcn3_b, tmp, 256, 2048, 4096);
    inorm(tmp, ga, 256, 4096, nullptr, 1);

    // ===== Res blocks (reflect-pad 3x3 convs, 256 ch, 64x64, implicit) =====
    ConvGeom gr = {256, 64, 64, 3, 3, 9, 1, 1, 64};
    conv_refl(rb1_w1, 2304, ga, rb1_b1, tmp, 256, 2304, 4096, gr);
    inorm(tmp, gb, 256, 4096, nullptr, 1);
    conv_refl(rb1_w2, 2304, gb, rb1_b2, tmp, 256, 2304, 4096, gr);
    inorm(tmp, ga, 256, 4096, ga, 0);

    conv_refl(rb2_w1, 2304, ga, rb2_b1, tmp, 256, 2304, 4096, gr);
    inorm(tmp, gb, 256, 4096, nullptr, 1);
    conv_refl(rb2_w2, 2304, gb, rb2_b2, tmp, 256, 2304, 4096, gr);
    inorm(tmp, out_h, 256, 4096, ga, 0);
}